// round 1
// baseline (speedup 1.0000x reference)
#include <cuda_runtime.h>
#include <cuda_bf16.h>

#define NN 100000

// Scratch (device globals — no allocation allowed)
__device__ __align__(16) float g_y[2][NN * 16];     // x @ w_nbr        (layer-1 neighbor proj)
__device__ __align__(16) float g_agg1[2][NN * 16];  // init x@w_self+b, then += segsum(y[src])
__device__ __align__(16) float g_h1[2][NN * 16];    // relu(agg1)
__device__ __align__(16) float g_agg2[2][NN * 16];  // init 0, then += segsum(h1[src])
__device__ __align__(16) float g_mol[NN * 100];     // concat(p, l)

__device__ __forceinline__ void atomicAddF4(float4* p, float4 v) {
#if defined(__CUDA_ARCH__) && __CUDA_ARCH__ >= 900
    atomicAdd(p, v);
#else
    float* f = (float*)p;
    atomicAdd(f + 0, v.x);
    atomicAdd(f + 1, v.y);
    atomicAdd(f + 2, v.z);
    atomicAdd(f + 3, v.w);
#endif
}

// ---------------------------------------------------------------------------
// Kernel 1: fused layer-1 projection.
//   y    = x @ w_nbr                      [N,16]
//   agg1 = x @ w_self + b   (initializer) [N,16]
//   agg2 = 0                (initializer) [N,16]
// Block: 256 threads, 32 rows/block. x tile + both weights staged in smem.
// ---------------------------------------------------------------------------
__global__ void proj_kernel(const float* __restrict__ x,
                            const float* __restrict__ w_self,
                            const float* __restrict__ w_nbr,
                            const float* __restrict__ bias,
                            int b, int N) {
    __shared__ __align__(16) float xs[32][128];
    __shared__ __align__(16) float ws[128][32];  // cols 0-15: w_nbr, 16-31: w_self
    int t = threadIdx.x;

    for (int i = t; i < 2048; i += 256) {
        int k = i >> 4, o = i & 15;
        ws[k][o] = w_nbr[i];
        ws[k][o + 16] = w_self[i];
    }

    int row0 = blockIdx.x << 5;
    const float4* x4 = (const float4*)x;
    float4* xs4 = (float4*)xs;
    int base = row0 * 32;  // row = 32 float4
    int lim = N * 32;
    for (int i = t; i < 1024; i += 256) {
        int g = base + i;
        xs4[i] = (g < lim) ? x4[g] : make_float4(0.f, 0.f, 0.f, 0.f);
    }
    __syncthreads();

    int og = (t & 7) << 2;  // output group (0..28 step 4)
    int r = t >> 3;         // row in tile (0..31)
    float4 acc = make_float4(0.f, 0.f, 0.f, 0.f);
#pragma unroll 32
    for (int k = 0; k < 128; k++) {
        float xv = xs[r][k];
        float4 wv = *(const float4*)&ws[k][og];
        acc.x = fmaf(xv, wv.x, acc.x);
        acc.y = fmaf(xv, wv.y, acc.y);
        acc.z = fmaf(xv, wv.z, acc.z);
        acc.w = fmaf(xv, wv.w, acc.w);
    }

    int row = row0 + r;
    if (row < N) {
        if (og < 16) {
            *(float4*)(g_y[b] + row * 16 + og) = acc;
            *(float4*)(g_agg2[b] + row * 16 + og) = make_float4(0.f, 0.f, 0.f, 0.f);
        } else {
            int o = og - 16;
            float4 bb = *(const float4*)(bias + o);
            acc.x += bb.x; acc.y += bb.y; acc.z += bb.z; acc.w += bb.w;
            *(float4*)(g_agg1[b] + row * 16 + o) = acc;
        }
    }
}

// ---------------------------------------------------------------------------
// Kernel 2: edge aggregation (scatter-add), 4 threads per edge (16B each).
// Gather source & scatter dest are 6.4MB each -> L2 resident.
// ---------------------------------------------------------------------------
__global__ void agg_kernel(const int* __restrict__ src,
                           const int* __restrict__ dst,
                           int b, int layer, int E) {
    int i = blockIdx.x * blockDim.x + threadIdx.x;
    int e = i >> 2;
    if (e >= E) return;
    int q = (i & 3) << 2;
    int s = __ldg(src + e);
    int d = __ldg(dst + e);
    const float* v = layer ? g_h1[b] : g_y[b];
    float* agg = layer ? g_agg2[b] : g_agg1[b];
    float4 val = *(const float4*)(v + s * 16 + q);
    atomicAddF4((float4*)(agg + d * 16 + q), val);
}

// ---------------------------------------------------------------------------
// Kernel 3: h1 = relu(agg1)   (agg1 already holds self-term + bias + agg)
// ---------------------------------------------------------------------------
__global__ void relu_kernel(int b, int n4) {
    int i = blockIdx.x * blockDim.x + threadIdx.x;
    if (i >= n4) return;
    float4 v = ((const float4*)g_agg1[b])[i];
    v.x = fmaxf(v.x, 0.f);
    v.y = fmaxf(v.y, 0.f);
    v.z = fmaxf(v.z, 0.f);
    v.w = fmaxf(v.w, 0.f);
    ((float4*)g_h1[b])[i] = v;
}

// ---------------------------------------------------------------------------
// Kernel 4: layer-2 conv output.
//   mol[:, col0:col0+50] = h1 @ w_s + agg2 @ w_n + b
// Block: 256 threads = 4 rows x 64 lanes (50 active outputs).
// ---------------------------------------------------------------------------
__global__ void layer2_kernel(int b,
                              const float* __restrict__ w_s,
                              const float* __restrict__ w_n,
                              const float* __restrict__ bias,
                              int col0, int N) {
    __shared__ float hs[4][16];
    __shared__ float as_[4][16];
    __shared__ float ws1[16 * 50];
    __shared__ float ws2[16 * 50];
    __shared__ float bs[50];
    int t = threadIdx.x;
    for (int i = t; i < 800; i += 256) {
        ws1[i] = w_s[i];
        ws2[i] = w_n[i];
    }
    if (t < 50) bs[t] = bias[t];

    int row0 = blockIdx.x << 2;
    if (t < 64) {
        int r = t >> 4, k = t & 15;
        int row = row0 + r;
        hs[r][k] = (row < N) ? g_h1[b][row * 16 + k] : 0.f;
    } else if (t < 128) {
        int tt = t - 64;
        int r = tt >> 4, k = tt & 15;
        int row = row0 + r;
        as_[r][k] = (row < N) ? g_agg2[b][row * 16 + k] : 0.f;
    }
    __syncthreads();

    int o = t & 63;
    int r = t >> 6;
    int row = row0 + r;
    if (o < 50 && row < N) {
        float acc = bs[o];
#pragma unroll
        for (int k = 0; k < 16; k++) {
            acc = fmaf(hs[r][k], ws1[k * 50 + o], acc);
            acc = fmaf(as_[r][k], ws2[k * 50 + o], acc);
        }
        g_mol[row * 100 + col0 + o] = acc;
    }
}

// ---------------------------------------------------------------------------
// Kernel 5: MLP head. One thread per row; row (100 floats) in registers,
// all weights in smem (w_in transposed to [60][25] float4 for LDS.128
// uniform-broadcast reads).
// ---------------------------------------------------------------------------
__global__ __launch_bounds__(128)
void head_kernel(const float* __restrict__ action,
                 const float* __restrict__ w_in, const float* __restrict__ b_in,
                 const float* __restrict__ w_hid, const float* __restrict__ b_hid,
                 const float* __restrict__ w_out, const float* __restrict__ b_out,
                 float* __restrict__ out, int N) {
    __shared__ float4 wst[60 * 25];  // transposed w_in: [o][kk] -> 4 k-values
    __shared__ float wh[700];
    __shared__ float bi[60];
    __shared__ float bh[10];
    __shared__ float wo[10];
    __shared__ float bo;
    int t = threadIdx.x;
    for (int i = t; i < 1500; i += 128) {
        int o = i / 25, kk = i % 25;
        float4 v;
        v.x = w_in[(kk * 4 + 0) * 60 + o];
        v.y = w_in[(kk * 4 + 1) * 60 + o];
        v.z = w_in[(kk * 4 + 2) * 60 + o];
        v.w = w_in[(kk * 4 + 3) * 60 + o];
        wst[i] = v;
    }
    for (int i = t; i < 700; i += 128) wh[i] = w_hid[i];
    if (t < 60) bi[t] = b_in[t];
    if (t < 10) { bh[t] = b_hid[t]; wo[t] = w_out[t]; }
    if (t == 0) bo = b_out[0];
    __syncthreads();

    int row = blockIdx.x * 128 + t;
    if (row >= N) return;

    float4 xr[25];
    const float4* m4 = (const float4*)(g_mol + (size_t)row * 100);
#pragma unroll
    for (int i = 0; i < 25; i++) xr[i] = m4[i];

    float pol[10];
#pragma unroll
    for (int a = 0; a < 10; a++) pol[a] = bh[a];

    for (int o = 0; o < 60; o++) {
        float acc = bi[o];
        const float4* wc = wst + o * 25;
#pragma unroll
        for (int kk = 0; kk < 25; kk++) {
            float4 w4 = wc[kk];
            acc = fmaf(xr[kk].x, w4.x, acc);
            acc = fmaf(xr[kk].y, w4.y, acc);
            acc = fmaf(xr[kk].z, w4.z, acc);
            acc = fmaf(xr[kk].w, w4.w, acc);
        }
        float f = fmaxf(acc, 0.f);
#pragma unroll
        for (int a = 0; a < 10; a++) pol[a] = fmaf(f, wh[o * 10 + a], pol[a]);
    }

    const float* arow = action + (size_t)row * 10;
#pragma unroll
    for (int j = 0; j < 10; j++) {
        float av = arow[j];
#pragma unroll
        for (int a = 0; a < 10; a++) pol[a] = fmaf(av, wh[(60 + j) * 10 + a], pol[a]);
    }

    float res = bo;
#pragma unroll
    for (int a = 0; a < 10; a++) res = fmaf(fmaxf(pol[a], 0.f), wo[a], res);
    out[row] = res;
}

// ---------------------------------------------------------------------------
extern "C" void kernel_launch(void* const* d_in, const int* in_sizes, int n_in,
                              void* d_out, int out_size) {
    const float* px = (const float*)d_in[0];
    const int*   pe = (const int*)d_in[1];
    const float* lx = (const float*)d_in[2];
    const int*   le = (const int*)d_in[3];
    const float* action = (const float*)d_in[4];
    const float* wp1s = (const float*)d_in[5];
    const float* wp1n = (const float*)d_in[6];
    const float* bp1  = (const float*)d_in[7];
    const float* wp2s = (const float*)d_in[8];
    const float* wp2n = (const float*)d_in[9];
    const float* bp2  = (const float*)d_in[10];
    const float* wl1s = (const float*)d_in[11];
    const float* wl1n = (const float*)d_in[12];
    const float* bl1  = (const float*)d_in[13];
    const float* wl2s = (const float*)d_in[14];
    const float* wl2n = (const float*)d_in[15];
    const float* bl2  = (const float*)d_in[16];
    const float* w_in  = (const float*)d_in[17];
    const float* b_in  = (const float*)d_in[18];
    const float* w_hid = (const float*)d_in[19];
    const float* b_hid = (const float*)d_in[20];
    const float* w_out = (const float*)d_in[21];
    const float* b_out = (const float*)d_in[22];
    float* out = (float*)d_out;

    int N = in_sizes[0] / 128;
    int Es[2] = {in_sizes[1] / 2, in_sizes[3] / 2};
    const float* xs[2] = {px, lx};
    const int* es[2] = {pe, le};
    const float* w1s[2] = {wp1s, wl1s};
    const float* w1n[2] = {wp1n, wl1n};
    const float* b1[2]  = {bp1, bl1};
    const float* w2s[2] = {wp2s, wl2s};
    const float* w2n[2] = {wp2n, wl2n};
    const float* b2[2]  = {bp2, bl2};

    for (int b = 0; b < 2; b++) {
        int E = Es[b];
        proj_kernel<<<(N + 31) / 32, 256>>>(xs[b], w1s[b], w1n[b], b1[b], b, N);
        agg_kernel<<<(E * 4 + 255) / 256, 256>>>(es[b], es[b] + E, b, 0, E);
        relu_kernel<<<(N * 4 + 255) / 256, 256>>>(b, N * 4);
        agg_kernel<<<(E * 4 + 255) / 256, 256>>>(es[b], es[b] + E, b, 1, E);
        layer2_kernel<<<(N + 3) / 4, 256>>>(b, w2s[b], w2n[b], b2[b], 50 * b, N);
    }
    head_kernel<<<(N + 127) / 128, 128>>>(action, w_in, b_in, w_hid, b_hid,
                                          w_out, b_out, out, N);
}